// round 6
// baseline (speedup 1.0000x reference)
#include <cuda_runtime.h>

#define HID 4096
#define GATES (3*HID)
#define NVOCAB 256
#define ROWS_PER_BLOCK 8                 // 8 warps, warp-per-row
#define GRID3 (3 * GATES / ROWS_PER_BLOCK)   // 4608
#define GRID1 (GATES / ROWS_PER_BLOCK)       // 1536
#define GTAIL 8                          // last-K blocks do the gate pass

// Scratch (allocation-free rule: __device__ globals). 16B-aligned for float4.
__device__ __align__(16) float g_gi0[GATES];
__device__ __align__(16) float g_gh0[GATES];
__device__ __align__(16) float g_gh1[GATES];
__device__ __align__(16) float g_gi1[GATES];
__device__ __align__(16) float g_h0[HID];
__device__ __align__(16) float g_h1[HID];
__device__ unsigned long long g_tick0;   // monotonic, replay-safe (64-bit: no wrap)
__device__ unsigned long long g_tick1;

__device__ __forceinline__ float sigmoidf_(float v) {
    return 1.0f / (1.0f + __expf(-v));
}

// Warp dot over HID=4096; weights streamed evict-first (__ldcs) so scratch/x
// stay L2-resident.
__device__ __forceinline__ float warp_dot_row(const float4* __restrict__ w4,
                                              const float4* __restrict__ sx4,
                                              int lane) {
    float acc = 0.0f;
    #pragma unroll
    for (int i = 0; i < HID / 4 / 32; i++) {       // 32 iterations
        float4 a  = __ldcs(w4 + lane + 32 * i);
        float4 xv = sx4[lane + 32 * i];
        acc += a.x * xv.x + a.y * xv.y + a.z * xv.z + a.w * xv.w;
    }
    #pragma unroll
    for (int off = 16; off; off >>= 1)
        acc += __shfl_down_sync(0xffffffffu, acc, off);
    return acc;
}

// Elementwise GRU gate pass for one float4 item j4 (0..HID/4-1).
__device__ __forceinline__ void gate_item(
    int j4, const float* __restrict__ gi_, const float* __restrict__ gh_,
    const float* __restrict__ h_prev, float* __restrict__ h_out,
    float* __restrict__ out_h)
{
    const float4* gi = (const float4*)gi_;
    const float4* gh = (const float4*)gh_;
    float4 ir = gi[j4];
    float4 hr = gh[j4];
    float4 iz = gi[j4 + HID/4];
    float4 hz = gh[j4 + HID/4];
    float4 in_ = gi[j4 + 2*(HID/4)];
    float4 hn  = gh[j4 + 2*(HID/4)];
    float4 hp = ((const float4*)h_prev)[j4];
    float4 h;
    {
        float r = sigmoidf_(ir.x + hr.x), z = sigmoidf_(iz.x + hz.x);
        float n = tanhf(in_.x + r * hn.x); h.x = (1.0f - z) * n + z * hp.x;
    }
    {
        float r = sigmoidf_(ir.y + hr.y), z = sigmoidf_(iz.y + hz.y);
        float n = tanhf(in_.y + r * hn.y); h.y = (1.0f - z) * n + z * hp.y;
    }
    {
        float r = sigmoidf_(ir.z + hr.z), z = sigmoidf_(iz.z + hz.z);
        float n = tanhf(in_.z + r * hn.z); h.z = (1.0f - z) * n + z * hp.z;
    }
    {
        float r = sigmoidf_(ir.w + hr.w), z = sigmoidf_(iz.w + hz.w);
        float n = tanhf(in_.w + r * hn.w); h.w = (1.0f - z) * n + z * hp.w;
    }
    ((float4*)h_out)[j4] = h;
    ((float4*)out_h)[j4] = h;
}

// Last-GTAIL-of-round detection on a monotonic 64-bit ticket counter.
// Returns slice id [0, GTAIL) if this block is a tail worker (after spinning
// until the whole round has arrived), else -1. Replay-safe: counter is never
// reset; round boundaries are multiples of `grid`.
__device__ __forceinline__ int tail_slice(unsigned long long* ctr, int grid) {
    __threadfence();                      // publish this block's result writes
    __syncthreads();
    __shared__ unsigned long long s_ticket;
    if (threadIdx.x == 0) s_ticket = atomicAdd(ctr, 1ULL);
    __syncthreads();
    unsigned long long ticket = s_ticket;
    int pos = (int)(ticket % (unsigned long long)grid);
    if (pos < grid - GTAIL) return -1;
    unsigned long long target =
        (ticket / (unsigned long long)grid + 1ULL) * (unsigned long long)grid;
    if (threadIdx.x == 0) {
        while (*((volatile unsigned long long*)ctr) < target) __nanosleep(32);
    }
    __syncthreads();
    __threadfence();                      // acquire: see all round writes
    return pos - (grid - GTAIL);
}

// ---------------------------------------------------------------------------
// K1: gi0/gh0/gh1 matvecs (3 x 201 MB) + gate0 in the last-8-block tail.
// ---------------------------------------------------------------------------
__global__ __launch_bounds__(256) void mv3_kernel(
    const int* __restrict__ inp, const float* __restrict__ hidden,
    const float* __restrict__ emb,
    const float* __restrict__ Wih0, const float* __restrict__ Whh0,
    const float* __restrict__ Whh1,
    const float* __restrict__ bih0, const float* __restrict__ bhh0,
    const float* __restrict__ bhh1, float* __restrict__ out)
{
    __shared__ float sx[HID];
    const int warp = threadIdx.x >> 5;
    const int lane = threadIdx.x & 31;

    const int blocks_per_seg = GATES / ROWS_PER_BLOCK;   // 1536
    const int seg    = blockIdx.x / blocks_per_seg;      // 0,1,2
    const int segblk = blockIdx.x % blocks_per_seg;

    const float* W; const float* b; const float* x; float* y;
    if (seg == 0)      { W = Wih0; b = bih0; x = emb + (size_t)inp[0] * HID; y = g_gi0; }
    else if (seg == 1) { W = Whh0; b = bhh0; x = hidden;                     y = g_gh0; }
    else               { W = Whh1; b = bhh1; x = hidden + HID;               y = g_gh1; }

    for (int i = threadIdx.x; i < HID / 4; i += blockDim.x)
        ((float4*)sx)[i] = ((const float4*)x)[i];
    __syncthreads();

    const int row = segblk * ROWS_PER_BLOCK + warp;
    float acc = warp_dot_row((const float4*)(W + (size_t)row * HID),
                             (const float4*)sx, lane);
    if (lane == 0) y[row] = acc + b[row];

    // ---- tail: last 8 blocks of the round compute h0_new ----
    int slice = tail_slice(&g_tick0, GRID3);
    if (slice >= 0 && threadIdx.x < 128) {
        const int j4 = slice * (HID / 4 / GTAIL) + threadIdx.x;  // 128 items/slice
        gate_item(j4, g_gi0, g_gh0, hidden, g_h0, out + NVOCAB);
    }
}

// ---------------------------------------------------------------------------
// K2: gi1 = W_ih1 @ h0_new (201 MB) + gate1 in the last-8-block tail.
// ---------------------------------------------------------------------------
__global__ __launch_bounds__(256) void mv1_kernel(
    const float* __restrict__ Wih1, const float* __restrict__ bih1,
    const float* __restrict__ hidden, float* __restrict__ out)
{
    __shared__ float sx[HID];
    const int warp = threadIdx.x >> 5;
    const int lane = threadIdx.x & 31;

    for (int i = threadIdx.x; i < HID / 4; i += blockDim.x)
        ((float4*)sx)[i] = ((const float4*)g_h0)[i];
    __syncthreads();

    const int row = blockIdx.x * ROWS_PER_BLOCK + warp;
    float acc = warp_dot_row((const float4*)(Wih1 + (size_t)row * HID),
                             (const float4*)sx, lane);
    if (lane == 0) g_gi1[row] = acc + bih1[row];

    // ---- tail: last 8 blocks of the round compute h1_new ----
    int slice = tail_slice(&g_tick1, GRID1);
    if (slice >= 0 && threadIdx.x < 128) {
        const int j4 = slice * (HID / 4 / GTAIL) + threadIdx.x;
        gate_item(j4, g_gi1, g_gh1, hidden + HID, g_h1, out + NVOCAB + HID);
    }
}

// ---------------------------------------------------------------------------
// K3: decoder logits out[0:256] = W_dec @ h1_new + b_dec. 32 blocks.
// ---------------------------------------------------------------------------
__global__ __launch_bounds__(256) void dec_kernel(
    const float* __restrict__ Wdec, const float* __restrict__ bdec,
    float* __restrict__ out)
{
    __shared__ float sx[HID];
    const int warp = threadIdx.x >> 5;
    const int lane = threadIdx.x & 31;

    for (int i = threadIdx.x; i < HID / 4; i += blockDim.x)
        ((float4*)sx)[i] = ((const float4*)g_h1)[i];
    __syncthreads();

    const int row = blockIdx.x * ROWS_PER_BLOCK + warp;
    float acc = warp_dot_row((const float4*)(Wdec + (size_t)row * HID),
                             (const float4*)sx, lane);
    if (lane == 0) out[row] = acc + bdec[row];
}

// ---------------------------------------------------------------------------
// Inputs (metadata order):
// 0 inp(int32,1) 1 hidden(2*4096) 2 emb(256*4096)
// 3 W_ih0 4 W_hh0 5 b_ih0 6 b_hh0
// 7 W_ih1 8 W_hh1 9 b_ih1 10 b_hh1
// 11 W_dec 12 b_dec
// Output: [logits(256) | h0_new(4096) | h1_new(4096)]
// ---------------------------------------------------------------------------
extern "C" void kernel_launch(void* const* d_in, const int* in_sizes, int n_in,
                              void* d_out, int out_size)
{
    const int*   inp    = (const int*)  d_in[0];
    const float* hidden = (const float*)d_in[1];
    const float* emb    = (const float*)d_in[2];
    const float* Wih0   = (const float*)d_in[3];
    const float* Whh0   = (const float*)d_in[4];
    const float* bih0   = (const float*)d_in[5];
    const float* bhh0   = (const float*)d_in[6];
    const float* Wih1   = (const float*)d_in[7];
    const float* Whh1   = (const float*)d_in[8];
    const float* bih1   = (const float*)d_in[9];
    const float* bhh1   = (const float*)d_in[10];
    const float* Wdec   = (const float*)d_in[11];
    const float* bdec   = (const float*)d_in[12];
    float* out = (float*)d_out;

    mv3_kernel<<<GRID3, 256>>>(inp, hidden, emb, Wih0, Whh0, Whh1,
                               bih0, bhh0, bhh1, out);
    mv1_kernel<<<GRID1, 256>>>(Wih1, bih1, hidden, out);
    dec_kernel<<<NVOCAB / ROWS_PER_BLOCK, 256>>>(Wdec, bdec, out);
}

// round 7
// speedup vs baseline: 1.0036x; 1.0036x over previous
#include <cuda_runtime.h>

#define HID 4096
#define GATES (3*HID)
#define NVOCAB 256
#define NBLK 592                    // 4 blocks/SM x 148 SMs, single wave
#define WARPS_TOT (NBLK * 8)        // 4736
#define ROWS3 (3 * GATES)           // 36864
#define GTAIL 8                     // last-K ticket blocks run the gate pass

// Scratch (allocation-free rule: __device__ globals). 16B-aligned for float4.
__device__ __align__(16) float g_gi0[GATES];
__device__ __align__(16) float g_gh0[GATES];
__device__ __align__(16) float g_gh1[GATES];
__device__ __align__(16) float g_gi1[GATES];
__device__ __align__(16) float g_h0[HID];
__device__ __align__(16) float g_h1[HID];
__device__ unsigned long long g_tick0;   // monotonic, replay-safe
__device__ unsigned long long g_tick1;

__device__ __forceinline__ float sigmoidf_(float v) {
    return 1.0f / (1.0f + __expf(-v));
}

// Warp dot over HID=4096 with explicit 4-wide load batching (16 independent
// LDG.128-bytes in flight per warp per step). Weights evict-first (__ldcs).
__device__ __forceinline__ float warp_dot_row(const float4* __restrict__ w4,
                                              const float4* __restrict__ sx4,
                                              int lane) {
    float acc = 0.0f;
    #pragma unroll
    for (int i = 0; i < 32; i += 4) {
        float4 a0 = __ldcs(w4 + lane + 32 * (i + 0));
        float4 a1 = __ldcs(w4 + lane + 32 * (i + 1));
        float4 a2 = __ldcs(w4 + lane + 32 * (i + 2));
        float4 a3 = __ldcs(w4 + lane + 32 * (i + 3));
        float4 x0 = sx4[lane + 32 * (i + 0)];
        float4 x1 = sx4[lane + 32 * (i + 1)];
        float4 x2 = sx4[lane + 32 * (i + 2)];
        float4 x3 = sx4[lane + 32 * (i + 3)];
        acc += a0.x * x0.x + a0.y * x0.y + a0.z * x0.z + a0.w * x0.w;
        acc += a1.x * x1.x + a1.y * x1.y + a1.z * x1.z + a1.w * x1.w;
        acc += a2.x * x2.x + a2.y * x2.y + a2.z * x2.z + a2.w * x2.w;
        acc += a3.x * x3.x + a3.y * x3.y + a3.z * x3.z + a3.w * x3.w;
    }
    #pragma unroll
    for (int off = 16; off; off >>= 1)
        acc += __shfl_down_sync(0xffffffffu, acc, off);
    return acc;
}

// Elementwise GRU gate pass for one float4 item j4 (0..HID/4-1).
__device__ __forceinline__ void gate_item(
    int j4, const float* __restrict__ gi_, const float* __restrict__ gh_,
    const float* __restrict__ h_prev, float* __restrict__ h_out,
    float* __restrict__ out_h)
{
    const float4* gi = (const float4*)gi_;
    const float4* gh = (const float4*)gh_;
    float4 ir = gi[j4];
    float4 hr = gh[j4];
    float4 iz = gi[j4 + HID/4];
    float4 hz = gh[j4 + HID/4];
    float4 in_ = gi[j4 + 2*(HID/4)];
    float4 hn  = gh[j4 + 2*(HID/4)];
    float4 hp = ((const float4*)h_prev)[j4];
    float4 h;
    {
        float r = sigmoidf_(ir.x + hr.x), z = sigmoidf_(iz.x + hz.x);
        float n = tanhf(in_.x + r * hn.x); h.x = (1.0f - z) * n + z * hp.x;
    }
    {
        float r = sigmoidf_(ir.y + hr.y), z = sigmoidf_(iz.y + hz.y);
        float n = tanhf(in_.y + r * hn.y); h.y = (1.0f - z) * n + z * hp.y;
    }
    {
        float r = sigmoidf_(ir.z + hr.z), z = sigmoidf_(iz.z + hz.z);
        float n = tanhf(in_.z + r * hn.z); h.z = (1.0f - z) * n + z * hp.z;
    }
    {
        float r = sigmoidf_(ir.w + hr.w), z = sigmoidf_(iz.w + hz.w);
        float n = tanhf(in_.w + r * hn.w); h.w = (1.0f - z) * n + z * hp.w;
    }
    ((float4*)h_out)[j4] = h;
    ((float4*)out_h)[j4] = h;
}

// Last-GTAIL-of-round detection on a monotonic 64-bit ticket counter.
// slot: a shared-memory cell (reused smem) for broadcasting the ticket.
// Returns slice id [0,GTAIL) for tail workers (after spinning), else -1.
__device__ __forceinline__ int tail_slice(unsigned long long* ctr,
                                          unsigned long long* slot, int grid) {
    __threadfence();                      // publish this block's writes
    __syncthreads();                      // all warps done with smem too
    if (threadIdx.x == 0) *slot = atomicAdd(ctr, 1ULL);
    __syncthreads();
    unsigned long long ticket = *slot;
    int pos = (int)(ticket % (unsigned long long)grid);
    if (pos < grid - GTAIL) return -1;
    unsigned long long target =
        (ticket / (unsigned long long)grid + 1ULL) * (unsigned long long)grid;
    if (threadIdx.x == 0) {
        while (*((volatile unsigned long long*)ctr) < target) __nanosleep(32);
    }
    __syncthreads();
    __threadfence();                      // acquire: see all round writes
    return pos - (grid - GTAIL);
}

// ---------------------------------------------------------------------------
// K1: flat 36864-row matvec over {W_ih0, W_hh0, W_hh1} (603 MB), warp-balanced
// row striding, + gate0 in the last-8-ticket tail. Grid = 592 (single wave).
// ---------------------------------------------------------------------------
__global__ __launch_bounds__(256, 4) void mv3_kernel(
    const int* __restrict__ inp, const float* __restrict__ hidden,
    const float* __restrict__ emb,
    const float* __restrict__ Wih0, const float* __restrict__ Whh0,
    const float* __restrict__ Whh1,
    const float* __restrict__ bih0, const float* __restrict__ bhh0,
    const float* __restrict__ bhh1, float* __restrict__ out)
{
    __shared__ __align__(16) float sx[3 * HID];   // 48 KB: x0 | h0 | h1
    const int warp = threadIdx.x >> 5;
    const int lane = threadIdx.x & 31;

    // Stage all three x vectors: emb row, hidden[0], hidden[1].
    {
        const float4* e4 = (const float4*)(emb + (size_t)inp[0] * HID);
        const float4* h4 = (const float4*)hidden;          // 2*HID contiguous
        float4* s4 = (float4*)sx;
        for (int i = threadIdx.x; i < 3 * HID / 4; i += 256)
            s4[i] = (i < HID / 4) ? e4[i] : h4[i - HID / 4];
    }
    __syncthreads();

    const int gw = blockIdx.x * 8 + warp;                  // 0..4735
    for (int r = gw; r < ROWS3; r += WARPS_TOT) {          // 7-8 rows/warp
        const int m  = r / GATES;                          // which matrix
        const int lr = r - m * GATES;                      // row in matrix
        const float* W; const float* b; float* y;
        if (m == 0)      { W = Wih0; b = bih0; y = g_gi0; }
        else if (m == 1) { W = Whh0; b = bhh0; y = g_gh0; }
        else             { W = Whh1; b = bhh1; y = g_gh1; }
        float acc = warp_dot_row((const float4*)(W + (size_t)lr * HID),
                                 (const float4*)(sx + m * HID), lane);
        if (lane == 0) y[lr] = acc + b[lr];
    }

    // ---- tail: last 8 ticket blocks compute h0_new ----
    int slice = tail_slice(&g_tick0, (unsigned long long*)sx, NBLK);
    if (slice >= 0 && threadIdx.x < 128) {
        const int j4 = slice * (HID / 4 / GTAIL) + threadIdx.x;
        gate_item(j4, g_gi0, g_gh0, hidden, g_h0, out + NVOCAB);
    }
}

// ---------------------------------------------------------------------------
// K2: gi1 = W_ih1 @ h0_new (201 MB), warp-balanced, + gate1 tail. Grid = 592.
// ---------------------------------------------------------------------------
__global__ __launch_bounds__(256, 4) void mv1_kernel(
    const float* __restrict__ Wih1, const float* __restrict__ bih1,
    const float* __restrict__ hidden, float* __restrict__ out)
{
    __shared__ __align__(16) float sx[HID];
    const int warp = threadIdx.x >> 5;
    const int lane = threadIdx.x & 31;

    for (int i = threadIdx.x; i < HID / 4; i += 256)
        ((float4*)sx)[i] = ((const float4*)g_h0)[i];
    __syncthreads();

    const int gw = blockIdx.x * 8 + warp;
    for (int r = gw; r < GATES; r += WARPS_TOT) {          // 2-3 rows/warp
        float acc = warp_dot_row((const float4*)(Wih1 + (size_t)r * HID),
                                 (const float4*)sx, lane);
        if (lane == 0) g_gi1[r] = acc + bih1[r];
    }

    // ---- tail: last 8 ticket blocks compute h1_new ----
    int slice = tail_slice(&g_tick1, (unsigned long long*)sx, NBLK);
    if (slice >= 0 && threadIdx.x < 128) {
        const int j4 = slice * (HID / 4 / GTAIL) + threadIdx.x;
        gate_item(j4, g_gi1, g_gh1, hidden + HID, g_h1, out + NVOCAB + HID);
    }
}

// ---------------------------------------------------------------------------
// K3: decoder logits out[0:256] = W_dec @ h1_new + b_dec. 32 blocks.
// ---------------------------------------------------------------------------
__global__ __launch_bounds__(256) void dec_kernel(
    const float* __restrict__ Wdec, const float* __restrict__ bdec,
    float* __restrict__ out)
{
    __shared__ __align__(16) float sx[HID];
    const int warp = threadIdx.x >> 5;
    const int lane = threadIdx.x & 31;

    for (int i = threadIdx.x; i < HID / 4; i += 256)
        ((float4*)sx)[i] = ((const float4*)g_h1)[i];
    __syncthreads();

    const int row = blockIdx.x * 8 + warp;
    float acc = warp_dot_row((const float4*)(Wdec + (size_t)row * HID),
                             (const float4*)sx, lane);
    if (lane == 0) out[row] = acc + bdec[row];
}

// ---------------------------------------------------------------------------
// Inputs (metadata order):
// 0 inp(int32,1) 1 hidden(2*4096) 2 emb(256*4096)
// 3 W_ih0 4 W_hh0 5 b_ih0 6 b_hh0
// 7 W_ih1 8 W_hh1 9 b_ih1 10 b_hh1
// 11 W_dec 12 b_dec
// Output: [logits(256) | h0_new(4096) | h1_new(4096)]
// ---------------------------------------------------------------------------
extern "C" void kernel_launch(void* const* d_in, const int* in_sizes, int n_in,
                              void* d_out, int out_size)
{
    const int*   inp    = (const int*)  d_in[0];
    const float* hidden = (const float*)d_in[1];
    const float* emb    = (const float*)d_in[2];
    const float* Wih0   = (const float*)d_in[3];
    const float* Whh0   = (const float*)d_in[4];
    const float* bih0   = (const float*)d_in[5];
    const float* bhh0   = (const float*)d_in[6];
    const float* Wih1   = (const float*)d_in[7];
    const float* Whh1   = (const float*)d_in[8];
    const float* bih1   = (const float*)d_in[9];
    const float* bhh1   = (const float*)d_in[10];
    const float* Wdec   = (const float*)d_in[11];
    const float* bdec   = (const float*)d_in[12];
    float* out = (float*)d_out;

    mv3_kernel<<<NBLK, 256>>>(inp, hidden, emb, Wih0, Whh0, Whh1,
                              bih0, bhh0, bhh1, out);
    mv1_kernel<<<NBLK, 256>>>(Wih1, bih1, hidden, out);
    dec_kernel<<<NVOCAB / 8, 256>>>(Wdec, bdec, out);
}